// round 2
// baseline (speedup 1.0000x reference)
#include <cuda_runtime.h>
#include <math.h>

// ---------------------------------------------------------------------------
// Problem constants
// ---------------------------------------------------------------------------
#define Bc   16
#define Sc   8192
#define Dc   512
#define Hc   8
#define HDc  64
#define NSc  3
// chunks per scale: 16, 8, 4  (512 dilated rows per chunk each)
#define CHUNKS_PER_B   28
#define NSLOTS         (Bc * CHUNKS_PER_B)     // 448
#define ROWS_PER_CHUNK 512
#define PSTRIDE        516                     // 512 acc + m + l, padded to 16B multiple

// ---------------------------------------------------------------------------
// Device scratch (static — no allocations allowed)
// ---------------------------------------------------------------------------
__device__ float g_q[Bc * Dc];                         // q = dh@Wq + bq
__device__ float g_qk[NSc * Bc * Hc * Dc];             // Wk_h^T q  * inv_scale
__device__ float g_qb[NSc * Bc * Hc];                  // q·bk_h    * inv_scale
__device__ float g_sw[NSc];                            // softmax(scale_weights)
__device__ float g_part[(size_t)NSLOTS * 2 * Hc * PSTRIDE]; // online-softmax partials
__device__ float g_combined[Bc * Dc];

// ---------------------------------------------------------------------------
// k1: q projection (+ softmax of scale weights)
//   grid (B, 4), block 128
// ---------------------------------------------------------------------------
__global__ void k1_qproj(const float* __restrict__ dh,
                         const float* __restrict__ Wq,
                         const float* __restrict__ bq,
                         const float* __restrict__ sw_in)
{
    __shared__ float ds[Dc];
    const int b = blockIdx.x;
    const int d = blockIdx.y * 128 + threadIdx.x;
    for (int e = threadIdx.x; e < Dc; e += 128) ds[e] = dh[b * Dc + e];
    __syncthreads();

    float a = bq[d];
    #pragma unroll 8
    for (int e = 0; e < Dc; e++) a += ds[e] * Wq[(size_t)e * Dc + d];
    g_q[b * Dc + d] = a;

    if (blockIdx.x == 0 && blockIdx.y == 0 && threadIdx.x == 0) {
        float m = fmaxf(sw_in[0], fmaxf(sw_in[1], sw_in[2]));
        float e0 = __expf(sw_in[0] - m);
        float e1 = __expf(sw_in[1] - m);
        float e2 = __expf(sw_in[2] - m);
        float s = e0 + e1 + e2;
        g_sw[0] = e0 / s; g_sw[1] = e1 / s; g_sw[2] = e2 / s;
    }
}

// ---------------------------------------------------------------------------
// k2: qk[i,b,h,e] = inv_scale * sum_hd q[b,h,hd] * Wk[i][e, h*HD+hd]
//     qb[i,b,h]   = inv_scale * sum_hd q[b,h,hd] * bk[i][h*HD+hd]
//   grid NS*B, block 256 (8 warps; one warp per (h,e) task)
// ---------------------------------------------------------------------------
__global__ void k2_qkproj(const float* __restrict__ Wk,
                          const float* __restrict__ bk)
{
    __shared__ float qs[Dc];
    const int i = blockIdx.x / Bc;
    const int b = blockIdx.x % Bc;
    const int tid = threadIdx.x, lane = tid & 31, wid = tid >> 5;

    for (int e = tid; e < Dc; e += 256) qs[e] = g_q[b * Dc + e];
    __syncthreads();

    const float* Wki = Wk + (size_t)i * Dc * Dc;
    const float inv_scale = 0.125f;   // 1/sqrt(64)

    for (int t = wid; t < Hc * Dc; t += 8) {
        const int h = t >> 9;          // t / 512
        const int e = t & 511;
        const float* wp = Wki + (size_t)e * Dc + h * HDc;
        float v = qs[h * HDc + lane]      * wp[lane]
                + qs[h * HDc + 32 + lane] * wp[32 + lane];
        #pragma unroll
        for (int off = 16; off; off >>= 1) v += __shfl_xor_sync(0xffffffffu, v, off);
        if (lane == 0)
            g_qk[(((size_t)i * Bc + b) * Hc + h) * Dc + e] = v * inv_scale;
    }

    // bias term: one warp per head
    {
        const int h = wid;
        const float* bp = bk + (size_t)i * Dc + h * HDc;
        float v = qs[h * HDc + lane]      * bp[lane]
                + qs[h * HDc + 32 + lane] * bp[32 + lane];
        #pragma unroll
        for (int off = 16; off; off >>= 1) v += __shfl_xor_sync(0xffffffffu, v, off);
        if (lane == 0)
            g_qb[((size_t)i * Bc + b) * Hc + h] = v * inv_scale;
    }
}

// ---------------------------------------------------------------------------
// k3: main streaming attention pass (online softmax, 2 heads per warp,
//     1-deep software pipeline on the row loads for MLP)
//   grid = 448 slots, block 256 (8 warps: 2 row-groups x 4 head-pairs)
// ---------------------------------------------------------------------------
__device__ __forceinline__ float dot4(float4 a, float4 b) {
    return a.x * b.x + a.y * b.y + a.z * b.z + a.w * b.w;
}

__global__ void __launch_bounds__(256, 2)
k3_attn(const float* __restrict__ enc)
{
    const int slot = blockIdx.x;                 // 0..447
    const int b = slot / CHUNKS_PER_B;
    const int r = slot - b * CHUNKS_PER_B;
    int scale, chunk;
    if (r < 16)      { scale = 0; chunk = r; }
    else if (r < 24) { scale = 1; chunk = r - 16; }
    else             { scale = 2; chunk = r - 24; }
    const int dil = 1 << scale;

    const int lane = threadIdx.x & 31;
    const int wid  = threadIdx.x >> 5;
    const int grp  = wid >> 2;                   // row parity
    const int hp   = wid & 3;
    const int h0   = hp * 2;

    // load per-warp query vectors (2 heads) into registers
    const float4* qkp0 = (const float4*)(g_qk + (((size_t)scale * Bc + b) * Hc + h0)     * Dc);
    const float4* qkp1 = (const float4*)(g_qk + (((size_t)scale * Bc + b) * Hc + h0 + 1) * Dc);
    float4 qk0[4], qk1[4];
    #pragma unroll
    for (int k = 0; k < 4; k++) {
        qk0[k] = qkp0[k * 32 + lane];
        qk1[k] = qkp1[k * 32 + lane];
    }
    const float sb0 = g_qb[((size_t)scale * Bc + b) * Hc + h0];
    const float sb1 = g_qb[((size_t)scale * Bc + b) * Hc + h0 + 1];

    float m0 = -1e30f, l0 = 0.f, m1 = -1e30f, l1 = 0.f;
    float acc0[16], acc1[16];
    #pragma unroll
    for (int k = 0; k < 16; k++) { acc0[k] = 0.f; acc1[k] = 0.f; }

    const float4* base =
        (const float4*)(enc + ((size_t)b * Sc + (size_t)chunk * ROWS_PER_CHUNK * dil) * Dc);
    const int rowstride4 = dil * (Dc / 4);       // float4 units between dilated rows

    // ---- software-pipelined row loop: rows lr = grp, grp+2, ... ----
    float4 x0, x1, x2, x3;            // current row
    {
        const float4* row = base + (size_t)grp * rowstride4;
        x0 = row[lane]; x1 = row[32 + lane]; x2 = row[64 + lane]; x3 = row[96 + lane];
    }

    for (int lr = grp; lr < ROWS_PER_CHUNK; lr += 2) {
        // prefetch next row (if any) before consuming current
        float4 n0, n1, n2, n3;
        const int nxt = lr + 2;
        if (nxt < ROWS_PER_CHUNK) {
            const float4* row = base + (size_t)nxt * rowstride4;
            n0 = row[lane]; n1 = row[32 + lane]; n2 = row[64 + lane]; n3 = row[96 + lane];
        }

        float s0 = dot4(x0, qk0[0]) + dot4(x1, qk0[1]) + dot4(x2, qk0[2]) + dot4(x3, qk0[3]);
        float s1 = dot4(x0, qk1[0]) + dot4(x1, qk1[1]) + dot4(x2, qk1[2]) + dot4(x3, qk1[3]);
        #pragma unroll
        for (int off = 16; off; off >>= 1) {
            s0 += __shfl_xor_sync(0xffffffffu, s0, off);
            s1 += __shfl_xor_sync(0xffffffffu, s1, off);
        }
        s0 += sb0;
        s1 += sb1;

        // head 0 online-softmax update (warp-uniform branch)
        if (s0 > m0) {
            float c = __expf(m0 - s0); m0 = s0; l0 *= c;
            #pragma unroll
            for (int k = 0; k < 16; k++) acc0[k] *= c;
        }
        float w0 = __expf(s0 - m0); l0 += w0;
        acc0[0]  += w0 * x0.x; acc0[1]  += w0 * x0.y; acc0[2]  += w0 * x0.z; acc0[3]  += w0 * x0.w;
        acc0[4]  += w0 * x1.x; acc0[5]  += w0 * x1.y; acc0[6]  += w0 * x1.z; acc0[7]  += w0 * x1.w;
        acc0[8]  += w0 * x2.x; acc0[9]  += w0 * x2.y; acc0[10] += w0 * x2.z; acc0[11] += w0 * x2.w;
        acc0[12] += w0 * x3.x; acc0[13] += w0 * x3.y; acc0[14] += w0 * x3.z; acc0[15] += w0 * x3.w;

        // head 1
        if (s1 > m1) {
            float c = __expf(m1 - s1); m1 = s1; l1 *= c;
            #pragma unroll
            for (int k = 0; k < 16; k++) acc1[k] *= c;
        }
        float w1 = __expf(s1 - m1); l1 += w1;
        acc1[0]  += w1 * x0.x; acc1[1]  += w1 * x0.y; acc1[2]  += w1 * x0.z; acc1[3]  += w1 * x0.w;
        acc1[4]  += w1 * x1.x; acc1[5]  += w1 * x1.y; acc1[6]  += w1 * x1.z; acc1[7]  += w1 * x1.w;
        acc1[8]  += w1 * x2.x; acc1[9]  += w1 * x2.y; acc1[10] += w1 * x2.z; acc1[11] += w1 * x2.w;
        acc1[12] += w1 * x3.x; acc1[13] += w1 * x3.y; acc1[14] += w1 * x3.z; acc1[15] += w1 * x3.w;

        x0 = n0; x1 = n1; x2 = n2; x3 = n3;
    }

    // write partials (per slot, group, head)
    {
        float* part = g_part + (((size_t)slot * 2 + grp) * Hc + h0) * PSTRIDE;
        float4* p4 = (float4*)part;
        #pragma unroll
        for (int k = 0; k < 4; k++)
            p4[k * 32 + lane] = make_float4(acc0[4 * k], acc0[4 * k + 1],
                                            acc0[4 * k + 2], acc0[4 * k + 3]);
        if (lane == 0) { part[512] = m0; part[513] = l0; }

        part += PSTRIDE;   // head h0+1
        p4 = (float4*)part;
        #pragma unroll
        for (int k = 0; k < 4; k++)
            p4[k * 32 + lane] = make_float4(acc1[4 * k], acc1[4 * k + 1],
                                            acc1[4 * k + 2], acc1[4 * k + 3]);
        if (lane == 0) { part[512] = m1; part[513] = l1; }
    }
}

// ---------------------------------------------------------------------------
// k4: combine partials per (b,h), project through Wv, weight by g_sw
//   grid B*H = 128, block 128
// ---------------------------------------------------------------------------
__global__ void k4_reduce(const float* __restrict__ Wv,
                          const float* __restrict__ bv)
{
    __shared__ float ctx[Dc];
    const int b = blockIdx.x >> 3;
    const int h = blockIdx.x & 7;
    const int tid = threadIdx.x;

    float comb = 0.f;   // valid for tid < 64 (hd = tid)

    for (int i = 0; i < NSc; i++) {
        const int C   = 16 >> i;                       // 16, 8, 4
        const int off = (i == 0) ? 0 : (i == 1 ? 16 : 24);
        const int P   = C * 2;

        // global max / denominator (redundant per thread; P <= 32)
        float M = -1e30f;
        for (int p = 0; p < P; p++) {
            const int slot = b * CHUNKS_PER_B + off + (p >> 1);
            const float* part = g_part + (((size_t)slot * 2 + (p & 1)) * Hc + h) * PSTRIDE;
            M = fmaxf(M, part[512]);
        }
        float L = 0.f;
        for (int p = 0; p < P; p++) {
            const int slot = b * CHUNKS_PER_B + off + (p >> 1);
            const float* part = g_part + (((size_t)slot * 2 + (p & 1)) * Hc + h) * PSTRIDE;
            L += part[513] * __expf(part[512] - M);
        }

        // merged (unnormalized) context vector
        for (int e = tid; e < Dc; e += 128) {
            float v = 0.f;
            for (int p = 0; p < P; p++) {
                const int slot = b * CHUNKS_PER_B + off + (p >> 1);
                const float* part = g_part + (((size_t)slot * 2 + (p & 1)) * Hc + h) * PSTRIDE;
                v += part[e] * __expf(part[512] - M);
            }
            ctx[e] = v;
        }
        __syncthreads();

        if (tid < 64) {
            const int c = h * HDc + tid;
            const float* Wvi = Wv + (size_t)i * Dc * Dc;
            float o = 0.f;
            #pragma unroll 8
            for (int e = 0; e < Dc; e++) o += ctx[e] * Wvi[(size_t)e * Dc + c];
            o = o / L + bv[(size_t)i * Dc + c];
            comb += g_sw[i] * o;
        }
        __syncthreads();   // ctx reused next scale
    }

    if (tid < 64) g_combined[b * Dc + h * HDc + tid] = comb;
}

// ---------------------------------------------------------------------------
// k5: context = combined @ Wo + bo
//   grid (B, 4), block 128
// ---------------------------------------------------------------------------
__global__ void k5_oproj(const float* __restrict__ Wo,
                         const float* __restrict__ bo,
                         float* __restrict__ out)
{
    __shared__ float cs[Dc];
    const int b = blockIdx.x;
    const int d = blockIdx.y * 128 + threadIdx.x;
    for (int e = threadIdx.x; e < Dc; e += 128) cs[e] = g_combined[b * Dc + e];
    __syncthreads();

    float a = bo[d];
    #pragma unroll 8
    for (int e = 0; e < Dc; e++) a += cs[e] * Wo[(size_t)e * Dc + d];
    out[b * Dc + d] = a;
}

// ---------------------------------------------------------------------------
// launch
// ---------------------------------------------------------------------------
extern "C" void kernel_launch(void* const* d_in, const int* in_sizes, int n_in,
                              void* d_out, int out_size)
{
    const float* dh   = (const float*)d_in[0];
    const float* enc  = (const float*)d_in[1];
    const float* Wq   = (const float*)d_in[2];
    const float* bq   = (const float*)d_in[3];
    const float* Wk   = (const float*)d_in[4];
    const float* bk   = (const float*)d_in[5];
    const float* Wv   = (const float*)d_in[6];
    const float* bv   = (const float*)d_in[7];
    const float* swi  = (const float*)d_in[8];
    const float* Wo   = (const float*)d_in[9];
    const float* bo   = (const float*)d_in[10];
    float* out = (float*)d_out;

    k1_qproj<<<dim3(Bc, 4), 128>>>(dh, Wq, bq, swi);
    k2_qkproj<<<NSc * Bc, 256>>>(Wk, bk);
    k3_attn<<<NSLOTS, 256>>>(enc);
    k4_reduce<<<Bc * Hc, 128>>>(Wv, bv);
    k5_oproj<<<dim3(Bc, 4), 128>>>(Wo, bo, out);
}

// round 3
// speedup vs baseline: 1.8863x; 1.8863x over previous
#include <cuda_runtime.h>
#include <math.h>

// ---------------------------------------------------------------------------
// Problem constants
// ---------------------------------------------------------------------------
#define Bc   16
#define Sc   8192
#define Dc   512
#define Hc   8
#define HDc  64
#define NSc  3
// chunks per scale: 16, 8, 4  (512 dilated rows per chunk each)
#define CHUNKS_PER_B   28
#define NSLOTS         (Bc * CHUNKS_PER_B)     // 448
#define ROWS_PER_CHUNK 512
#define PSTRIDE        516                     // 512 acc + m + l (16B multiple)
#define ESPLIT         4                       // e-chunks for projection kernels

// ---------------------------------------------------------------------------
// Device scratch (static — no allocations allowed)
// ---------------------------------------------------------------------------
__device__ float g_q[Bc * Dc];                               // q = dh@Wq + bq
__device__ float g_qk[NSc * Bc * Hc * Dc];                   // Wk_h^T q * inv_scale
__device__ float g_qb[NSc * Bc * Hc];                        // q·bk_h   * inv_scale
__device__ float g_sw[NSc];                                  // softmax(scale_weights)
__device__ float g_part[(size_t)NSLOTS * 2 * Hc * PSTRIDE];  // online-softmax partials
__device__ float g_ctx[NSc * Hc * Bc * Dc];                  // merged+normalized contexts
__device__ float g_vpart[ESPLIT * NSc * Hc * Bc * HDc];      // Wv projection partials

// ---------------------------------------------------------------------------
// k1: q projection (+ softmax of scale weights)   grid (B,4), block 128
// ---------------------------------------------------------------------------
__global__ void k1_qproj(const float* __restrict__ dh,
                         const float* __restrict__ Wq,
                         const float* __restrict__ bq,
                         const float* __restrict__ sw_in)
{
    __shared__ float ds[Dc];
    const int b = blockIdx.x;
    const int d = blockIdx.y * 128 + threadIdx.x;
    for (int e = threadIdx.x; e < Dc; e += 128) ds[e] = dh[b * Dc + e];
    __syncthreads();

    float a = bq[d];
    #pragma unroll 8
    for (int e = 0; e < Dc; e++) a += ds[e] * Wq[(size_t)e * Dc + d];
    g_q[b * Dc + d] = a;

    if (blockIdx.x == 0 && blockIdx.y == 0 && threadIdx.x == 0) {
        float m = fmaxf(sw_in[0], fmaxf(sw_in[1], sw_in[2]));
        float e0 = __expf(sw_in[0] - m);
        float e1 = __expf(sw_in[1] - m);
        float e2 = __expf(sw_in[2] - m);
        float s = e0 + e1 + e2;
        g_sw[0] = e0 / s; g_sw[1] = e1 / s; g_sw[2] = e2 / s;
    }
}

__device__ __forceinline__ float dot4(float4 a, float4 b) {
    return a.x * b.x + a.y * b.y + a.z * b.z + a.w * b.w;
}
__device__ __forceinline__ float4 fma4(float4 acc, float s, float4 v) {
    acc.x += s * v.x; acc.y += s * v.y; acc.z += s * v.z; acc.w += s * v.w;
    return acc;
}

// ---------------------------------------------------------------------------
// k2: qk[i,b,h,e] = inv_scale * q_h[b,:] @ Wk[i][e, h*64:+64]^T
//     tiled smem GEMM, grid (NS*H, ESPLIT), block 256
// ---------------------------------------------------------------------------
__global__ void k2_qkproj(const float* __restrict__ Wk,
                          const float* __restrict__ bk)
{
    const int i  = blockIdx.x >> 3;
    const int h  = blockIdx.x & 7;
    const int e0 = blockIdx.y * 128;
    const int t  = threadIdx.x;
    const float inv_scale = 0.125f;

    __shared__ float4 qs4[16][17];    // [b][hd4], padded
    __shared__ float4 Ws4[128][17];   // [e-local][hd4], padded

    // load q slice (16 x 64) — one float4 per thread
    if (t < 256) {
        const int b = t >> 4, hd4 = t & 15;
        qs4[b][hd4] = *(const float4*)(g_q + b * Dc + h * HDc + hd4 * 4);
    }
    // load Wk tile (128 e-rows x 64) coalesced
    {
        const float* Wki = Wk + (size_t)i * Dc * Dc;
        #pragma unroll
        for (int k = 0; k < 8; k++) {
            const int idx = t + k * 256;
            const int e = idx >> 4, hd4 = idx & 15;
            Ws4[e][hd4] = *(const float4*)(Wki + (size_t)(e0 + e) * Dc + h * HDc + hd4 * 4);
        }
    }
    __syncthreads();

    const int b  = t & 15;
    const int eL = t >> 4;            // 0..15, each owns 8 e's
    float acc[8];
    #pragma unroll
    for (int j = 0; j < 8; j++) acc[j] = 0.f;

    #pragma unroll
    for (int hd4 = 0; hd4 < 16; hd4++) {
        const float4 q4 = qs4[b][hd4];
        #pragma unroll
        for (int j = 0; j < 8; j++)
            acc[j] += dot4(q4, Ws4[eL * 8 + j][hd4]);
    }
    float* dst = g_qk + (((size_t)i * Bc + b) * Hc + h) * Dc + e0 + eL * 8;
    #pragma unroll
    for (int j = 0; j < 8; j++) dst[j] = acc[j] * inv_scale;

    // bias term (once per (i,h)): qb[i,b,h] = inv_scale * q_h[b,:]·bk_h
    if (blockIdx.y == 0 && t < 16) {
        float s = 0.f;
        #pragma unroll
        for (int hd4 = 0; hd4 < 16; hd4++) {
            const float4 b4 = *(const float4*)(bk + (size_t)i * Dc + h * HDc + hd4 * 4);
            s += dot4(qs4[t][hd4], b4);
        }
        g_qb[((size_t)i * Bc + t) * Hc + h] = s * inv_scale;
    }
}

// ---------------------------------------------------------------------------
// k3: main streaming attention pass (online softmax, 2 heads per warp,
//     1-deep software pipeline) — grid 448, block 256
// ---------------------------------------------------------------------------
__global__ void __launch_bounds__(256, 2)
k3_attn(const float* __restrict__ enc)
{
    const int slot = blockIdx.x;
    const int b = slot / CHUNKS_PER_B;
    const int r = slot - b * CHUNKS_PER_B;
    int scale, chunk;
    if (r < 16)      { scale = 0; chunk = r; }
    else if (r < 24) { scale = 1; chunk = r - 16; }
    else             { scale = 2; chunk = r - 24; }
    const int dil = 1 << scale;

    const int lane = threadIdx.x & 31;
    const int wid  = threadIdx.x >> 5;
    const int grp  = wid >> 2;
    const int h0   = (wid & 3) * 2;

    const float4* qkp0 = (const float4*)(g_qk + (((size_t)scale * Bc + b) * Hc + h0)     * Dc);
    const float4* qkp1 = (const float4*)(g_qk + (((size_t)scale * Bc + b) * Hc + h0 + 1) * Dc);
    float4 qk0[4], qk1[4];
    #pragma unroll
    for (int k = 0; k < 4; k++) {
        qk0[k] = qkp0[k * 32 + lane];
        qk1[k] = qkp1[k * 32 + lane];
    }
    const float sb0 = g_qb[((size_t)scale * Bc + b) * Hc + h0];
    const float sb1 = g_qb[((size_t)scale * Bc + b) * Hc + h0 + 1];

    float m0 = -1e30f, l0 = 0.f, m1 = -1e30f, l1 = 0.f;
    float acc0[16], acc1[16];
    #pragma unroll
    for (int k = 0; k < 16; k++) { acc0[k] = 0.f; acc1[k] = 0.f; }

    const float4* base =
        (const float4*)(enc + ((size_t)b * Sc + (size_t)chunk * ROWS_PER_CHUNK * dil) * Dc);
    const int rowstride4 = dil * (Dc / 4);

    float4 x0, x1, x2, x3;
    {
        const float4* row = base + (size_t)grp * rowstride4;
        x0 = row[lane]; x1 = row[32 + lane]; x2 = row[64 + lane]; x3 = row[96 + lane];
    }

    for (int lr = grp; lr < ROWS_PER_CHUNK; lr += 2) {
        float4 n0, n1, n2, n3;
        const int nxt = lr + 2;
        if (nxt < ROWS_PER_CHUNK) {
            const float4* row = base + (size_t)nxt * rowstride4;
            n0 = row[lane]; n1 = row[32 + lane]; n2 = row[64 + lane]; n3 = row[96 + lane];
        }

        float s0 = dot4(x0, qk0[0]) + dot4(x1, qk0[1]) + dot4(x2, qk0[2]) + dot4(x3, qk0[3]);
        float s1 = dot4(x0, qk1[0]) + dot4(x1, qk1[1]) + dot4(x2, qk1[2]) + dot4(x3, qk1[3]);
        #pragma unroll
        for (int off = 16; off; off >>= 1) {
            s0 += __shfl_xor_sync(0xffffffffu, s0, off);
            s1 += __shfl_xor_sync(0xffffffffu, s1, off);
        }
        s0 += sb0;
        s1 += sb1;

        if (s0 > m0) {
            float c = __expf(m0 - s0); m0 = s0; l0 *= c;
            #pragma unroll
            for (int k = 0; k < 16; k++) acc0[k] *= c;
        }
        float w0 = __expf(s0 - m0); l0 += w0;
        acc0[0]  += w0 * x0.x; acc0[1]  += w0 * x0.y; acc0[2]  += w0 * x0.z; acc0[3]  += w0 * x0.w;
        acc0[4]  += w0 * x1.x; acc0[5]  += w0 * x1.y; acc0[6]  += w0 * x1.z; acc0[7]  += w0 * x1.w;
        acc0[8]  += w0 * x2.x; acc0[9]  += w0 * x2.y; acc0[10] += w0 * x2.z; acc0[11] += w0 * x2.w;
        acc0[12] += w0 * x3.x; acc0[13] += w0 * x3.y; acc0[14] += w0 * x3.z; acc0[15] += w0 * x3.w;

        if (s1 > m1) {
            float c = __expf(m1 - s1); m1 = s1; l1 *= c;
            #pragma unroll
            for (int k = 0; k < 16; k++) acc1[k] *= c;
        }
        float w1 = __expf(s1 - m1); l1 += w1;
        acc1[0]  += w1 * x0.x; acc1[1]  += w1 * x0.y; acc1[2]  += w1 * x0.z; acc1[3]  += w1 * x0.w;
        acc1[4]  += w1 * x1.x; acc1[5]  += w1 * x1.y; acc1[6]  += w1 * x1.z; acc1[7]  += w1 * x1.w;
        acc1[8]  += w1 * x2.x; acc1[9]  += w1 * x2.y; acc1[10] += w1 * x2.z; acc1[11] += w1 * x2.w;
        acc1[12] += w1 * x3.x; acc1[13] += w1 * x3.y; acc1[14] += w1 * x3.z; acc1[15] += w1 * x3.w;

        x0 = n0; x1 = n1; x2 = n2; x3 = n3;
    }

    {
        float* part = g_part + (((size_t)slot * 2 + grp) * Hc + h0) * PSTRIDE;
        float4* p4 = (float4*)part;
        #pragma unroll
        for (int k = 0; k < 4; k++)
            p4[k * 32 + lane] = make_float4(acc0[4 * k], acc0[4 * k + 1],
                                            acc0[4 * k + 2], acc0[4 * k + 3]);
        if (lane == 0) { part[512] = m0; part[513] = l0; }

        part += PSTRIDE;
        p4 = (float4*)part;
        #pragma unroll
        for (int k = 0; k < 4; k++)
            p4[k * 32 + lane] = make_float4(acc1[4 * k], acc1[4 * k + 1],
                                            acc1[4 * k + 2], acc1[4 * k + 3]);
        if (lane == 0) { part[512] = m1; part[513] = l1; }
    }
}

// ---------------------------------------------------------------------------
// k4a: merge partials per (i,b,h) into normalized context vector
//   grid NS*B*H = 384, block 128
// ---------------------------------------------------------------------------
__global__ void k4a_merge()
{
    const int id = blockIdx.x;
    const int i = id >> 7;
    const int b = (id >> 3) & 15;
    const int h = id & 7;
    const int tid = threadIdx.x;

    const int C   = 16 >> i;                  // chunks: 16, 8, 4
    const int off = (i == 0) ? 0 : (i == 1 ? 16 : 24);
    const int P   = C * 2;                    // partials: 32, 16, 8

    __shared__ float sm[32], sl[32], coef[32];

    if (tid < P) {
        const int slot = b * CHUNKS_PER_B + off + (tid >> 1);
        const float* pp = g_part + (((size_t)slot * 2 + (tid & 1)) * Hc + h) * PSTRIDE;
        sm[tid] = pp[512];
        sl[tid] = pp[513];
    }
    __syncthreads();

    float M = -1e30f;
    for (int p = 0; p < P; p++) M = fmaxf(M, sm[p]);
    float L = 0.f;
    for (int p = 0; p < P; p++) L += sl[p] * __expf(sm[p] - M);

    if (tid < P) coef[tid] = __expf(sm[tid] - M) / L;
    __syncthreads();

    float4 v = make_float4(0.f, 0.f, 0.f, 0.f);
    for (int p = 0; p < P; p++) {
        const int slot = b * CHUNKS_PER_B + off + (p >> 1);
        const float4* pp4 = (const float4*)(g_part +
            (((size_t)slot * 2 + (p & 1)) * Hc + h) * PSTRIDE);
        v = fma4(v, coef[p], pp4[tid]);
    }
    float4* dst = (float4*)(g_ctx + (((size_t)i * Hc + h) * Bc + b) * Dc);
    dst[tid] = v;
}

// ---------------------------------------------------------------------------
// k4b: projection partial  out_p[i,h,b,hd] = ctx[i,h,b,e0:e0+128] @ Wv-slice
//   grid (NS*H, ESPLIT), block 256
// ---------------------------------------------------------------------------
__global__ void k4b_vproj(const float* __restrict__ Wv)
{
    const int i  = blockIdx.x >> 3;
    const int h  = blockIdx.x & 7;
    const int e0 = blockIdx.y * 128;
    const int t  = threadIdx.x;

    __shared__ float4 Ws4[128][17];   // Wv[e0+e][h*64 + hd]
    __shared__ float  cs[16][129];    // ctx[b][e-local]

    {
        const float* Wvi = Wv + (size_t)i * Dc * Dc;
        #pragma unroll
        for (int k = 0; k < 8; k++) {
            const int idx = t + k * 256;
            const int e = idx >> 4, hd4 = idx & 15;
            Ws4[e][hd4] = *(const float4*)(Wvi + (size_t)(e0 + e) * Dc + h * HDc + hd4 * 4);
        }
    }
    {
        const float* ctx = g_ctx + (((size_t)i * Hc + h) * Bc) * Dc;
        #pragma unroll
        for (int k = 0; k < 8; k++) {
            const int idx = t + k * 256;
            const int b = idx >> 7, e = idx & 127;
            cs[b][e] = ctx[(size_t)b * Dc + e0 + e];
        }
    }
    __syncthreads();

    const int b   = t & 15;
    const int hdL = t >> 4;           // 0..15 -> hd = hdL*4
    float4 acc = make_float4(0.f, 0.f, 0.f, 0.f);
    #pragma unroll 4
    for (int e = 0; e < 128; e++)
        acc = fma4(acc, cs[b][e], Ws4[e][hdL]);

    float4* dst = (float4*)(g_vpart +
        ((((size_t)blockIdx.y * NSc + i) * Hc + h) * Bc + b) * HDc + hdL * 4);
    *dst = acc;
}

// ---------------------------------------------------------------------------
// k5: combined = sum_i sw_i * (proj_i + bv_i);  out = combined @ Wo + bo
//   grid (B,4), block 128
// ---------------------------------------------------------------------------
__global__ void k5_oproj(const float* __restrict__ Wo,
                         const float* __restrict__ bo,
                         const float* __restrict__ bv,
                         float* __restrict__ out)
{
    __shared__ float cs[Dc];
    const int b = blockIdx.x;
    const int d = blockIdx.y * 128 + threadIdx.x;

    for (int e = threadIdx.x; e < Dc; e += 128) {
        const int h = e >> 6, hd = e & 63;
        float s = 0.f;
        #pragma unroll
        for (int i = 0; i < NSc; i++) {
            float v = bv[(size_t)i * Dc + e];
            #pragma unroll
            for (int p = 0; p < ESPLIT; p++)
                v += g_vpart[((((size_t)p * NSc + i) * Hc + h) * Bc + b) * HDc + hd];
            s += g_sw[i] * v;
        }
        cs[e] = s;
    }
    __syncthreads();

    float a = bo[d];
    #pragma unroll 8
    for (int e = 0; e < Dc; e++) a += cs[e] * Wo[(size_t)e * Dc + d];
    out[b * Dc + d] = a;
}

// ---------------------------------------------------------------------------
// launch
// ---------------------------------------------------------------------------
extern "C" void kernel_launch(void* const* d_in, const int* in_sizes, int n_in,
                              void* d_out, int out_size)
{
    const float* dh   = (const float*)d_in[0];
    const float* enc  = (const float*)d_in[1];
    const float* Wq   = (const float*)d_in[2];
    const float* bq   = (const float*)d_in[3];
    const float* Wk   = (const float*)d_in[4];
    const float* bk   = (const float*)d_in[5];
    const float* Wv   = (const float*)d_in[6];
    const float* bv   = (const float*)d_in[7];
    const float* swi  = (const float*)d_in[8];
    const float* Wo   = (const float*)d_in[9];
    const float* bo   = (const float*)d_in[10];
    float* out = (float*)d_out;

    k1_qproj<<<dim3(Bc, 4), 128>>>(dh, Wq, bq, swi);
    k2_qkproj<<<dim3(NSc * Hc, ESPLIT), 256>>>(Wk, bk);
    k3_attn<<<NSLOTS, 256>>>(enc);
    k4a_merge<<<NSc * Bc * Hc, 128>>>();
    k4b_vproj<<<dim3(NSc * Hc, ESPLIT), 256>>>(Wv);
    k5_oproj<<<dim3(Bc, 4), 128>>>(Wo, bo, bv, out);
}

// round 4
// speedup vs baseline: 2.3363x; 1.2386x over previous
#include <cuda_runtime.h>
#include <math.h>
#include <stdint.h>

// ---------------------------------------------------------------------------
// Problem constants
// ---------------------------------------------------------------------------
#define Bc   16
#define Sc   8192
#define Dc   512
#define Hc   8
#define HDc  64
#define NSc  3
// chunks per batch: scale0: 32, scale1: 16, scale2: 8  (256 dilated rows each)
#define CHUNKS_PER_B   56
#define NSLOTS         (Bc * CHUNKS_PER_B)     // 896
#define ROWS_PER_CHUNK 256
#define TILE           8                        // rows staged in smem per buffer
#define NTILES         (ROWS_PER_CHUNK / TILE)  // 32
#define PSTRIDE        516                      // 512 acc + m + l
#define ESPLIT         4

// ---------------------------------------------------------------------------
// Device scratch (static — no allocations allowed)
// ---------------------------------------------------------------------------
__device__ float g_q[Bc * Dc];
__device__ float g_qk[NSc * Bc * Hc * Dc];
__device__ float g_qb[NSc * Bc * Hc];
__device__ float g_sw[NSc];
__device__ float g_part[(size_t)NSLOTS * Hc * PSTRIDE];    // 1 partial per slot-head
__device__ float g_ctx[NSc * Hc * Bc * Dc];
__device__ float g_vpart[ESPLIT * NSc * Hc * Bc * HDc];

// ---------------------------------------------------------------------------
// helpers
// ---------------------------------------------------------------------------
__device__ __forceinline__ float dot4(float4 a, float4 b) {
    return a.x * b.x + a.y * b.y + a.z * b.z + a.w * b.w;
}
__device__ __forceinline__ float4 fma4(float4 acc, float s, float4 v) {
    acc.x += s * v.x; acc.y += s * v.y; acc.z += s * v.z; acc.w += s * v.w;
    return acc;
}
__device__ __forceinline__ void cp16(void* smem_dst, const void* gsrc) {
    uint32_t s = (uint32_t)__cvta_generic_to_shared(smem_dst);
    asm volatile("cp.async.ca.shared.global [%0], [%1], 16;" :: "r"(s), "l"(gsrc));
}
#define CP_COMMIT() asm volatile("cp.async.commit_group;")
#define CP_WAIT1()  asm volatile("cp.async.wait_group 1;")
#define CP_WAIT0()  asm volatile("cp.async.wait_group 0;")

// ---------------------------------------------------------------------------
// k1: q projection (+ softmax of scale weights)   grid (B,4), block 128
// ---------------------------------------------------------------------------
__global__ void k1_qproj(const float* __restrict__ dh,
                         const float* __restrict__ Wq,
                         const float* __restrict__ bq,
                         const float* __restrict__ sw_in)
{
    __shared__ float ds[Dc];
    const int b = blockIdx.x;
    const int d = blockIdx.y * 128 + threadIdx.x;
    for (int e = threadIdx.x; e < Dc; e += 128) ds[e] = dh[b * Dc + e];
    __syncthreads();

    float a = bq[d];
    #pragma unroll 8
    for (int e = 0; e < Dc; e++) a += ds[e] * Wq[(size_t)e * Dc + d];
    g_q[b * Dc + d] = a;

    if (blockIdx.x == 0 && blockIdx.y == 0 && threadIdx.x == 0) {
        float m = fmaxf(sw_in[0], fmaxf(sw_in[1], sw_in[2]));
        float e0 = __expf(sw_in[0] - m);
        float e1 = __expf(sw_in[1] - m);
        float e2 = __expf(sw_in[2] - m);
        float s = e0 + e1 + e2;
        g_sw[0] = e0 / s; g_sw[1] = e1 / s; g_sw[2] = e2 / s;
    }
}

// ---------------------------------------------------------------------------
// k2: qk[i,b,h,e] = inv_scale * q_h[b,:] @ Wk[i][e, h*64:+64]^T
//     tiled smem GEMM, grid (NS*H, ESPLIT), block 256
// ---------------------------------------------------------------------------
__global__ void k2_qkproj(const float* __restrict__ Wk,
                          const float* __restrict__ bk)
{
    const int i  = blockIdx.x >> 3;
    const int h  = blockIdx.x & 7;
    const int e0 = blockIdx.y * 128;
    const int t  = threadIdx.x;
    const float inv_scale = 0.125f;

    __shared__ float4 qs4[16][17];
    __shared__ float4 Ws4[128][17];

    {
        const int b = t >> 4, hd4 = t & 15;
        qs4[b][hd4] = *(const float4*)(g_q + b * Dc + h * HDc + hd4 * 4);
    }
    {
        const float* Wki = Wk + (size_t)i * Dc * Dc;
        #pragma unroll
        for (int k = 0; k < 8; k++) {
            const int idx = t + k * 256;
            const int e = idx >> 4, hd4 = idx & 15;
            Ws4[e][hd4] = *(const float4*)(Wki + (size_t)(e0 + e) * Dc + h * HDc + hd4 * 4);
        }
    }
    __syncthreads();

    const int b  = t & 15;
    const int eL = t >> 4;
    float acc[8];
    #pragma unroll
    for (int j = 0; j < 8; j++) acc[j] = 0.f;

    #pragma unroll
    for (int hd4 = 0; hd4 < 16; hd4++) {
        const float4 q4 = qs4[b][hd4];
        #pragma unroll
        for (int j = 0; j < 8; j++)
            acc[j] += dot4(q4, Ws4[eL * 8 + j][hd4]);
    }
    float* dst = g_qk + (((size_t)i * Bc + b) * Hc + h) * Dc + e0 + eL * 8;
    #pragma unroll
    for (int j = 0; j < 8; j++) dst[j] = acc[j] * inv_scale;

    if (blockIdx.y == 0 && t < 16) {
        float s = 0.f;
        #pragma unroll
        for (int hd4 = 0; hd4 < 16; hd4++) {
            const float4 b4 = *(const float4*)(bk + (size_t)i * Dc + h * HDc + hd4 * 4);
            s += dot4(qs4[t][hd4], b4);
        }
        g_qb[((size_t)i * Bc + t) * Hc + h] = s * inv_scale;
    }
}

// ---------------------------------------------------------------------------
// k3: streaming attention, smem-staged rows + cp.async double buffer
//   grid 896, block 256 (8 warps: 2 row-groups x 4 head-pairs)
// ---------------------------------------------------------------------------
__global__ void __launch_bounds__(256, 2)
k3_attn(const float* __restrict__ enc)
{
    __shared__ float4 s_buf[2][TILE][130];     // 130 = 128 + 2 pad (2080B row)
    __shared__ float  s_m[Hc], s_l[Hc];

    const int slot = blockIdx.x;
    const int b = slot / CHUNKS_PER_B;
    const int r = slot - b * CHUNKS_PER_B;
    int scale, chunk;
    if (r < 32)      { scale = 0; chunk = r; }
    else if (r < 48) { scale = 1; chunk = r - 32; }
    else             { scale = 2; chunk = r - 48; }
    const int dil = 1 << scale;

    const int tid  = threadIdx.x;
    const int lane = tid & 31;
    const int wid  = tid >> 5;
    const int grp  = wid >> 2;
    const int h0   = (wid & 3) * 2;

    // query vectors for 2 heads -> registers
    const float4* qkp0 = (const float4*)(g_qk + (((size_t)scale * Bc + b) * Hc + h0)     * Dc);
    const float4* qkp1 = (const float4*)(g_qk + (((size_t)scale * Bc + b) * Hc + h0 + 1) * Dc);
    float4 qk0[4], qk1[4];
    #pragma unroll
    for (int k = 0; k < 4; k++) {
        qk0[k] = qkp0[k * 32 + lane];
        qk1[k] = qkp1[k * 32 + lane];
    }
    const float sb0 = g_qb[((size_t)scale * Bc + b) * Hc + h0];
    const float sb1 = g_qb[((size_t)scale * Bc + b) * Hc + h0 + 1];

    float m0 = -1e30f, l0 = 0.f, m1 = -1e30f, l1 = 0.f;
    float acc0[16], acc1[16];
    #pragma unroll
    for (int k = 0; k < 16; k++) { acc0[k] = 0.f; acc1[k] = 0.f; }

    const float4* base =
        (const float4*)(enc + ((size_t)b * Sc + (size_t)chunk * ROWS_PER_CHUNK * dil) * Dc);
    const int rowstride4 = dil * (Dc / 4);

    // prologue: stage tile 0
    #pragma unroll
    for (int k = 0; k < 4; k++) {
        const int idx = tid + k * 256;
        const int rr = idx >> 7, c4 = idx & 127;
        cp16(&s_buf[0][rr][c4], base + (size_t)rr * rowstride4 + c4);
    }
    CP_COMMIT();

    for (int t = 0; t < NTILES; t++) {
        if (t + 1 < NTILES) {
            const int bsel = (t + 1) & 1;
            const int row0 = (t + 1) * TILE;
            #pragma unroll
            for (int k = 0; k < 4; k++) {
                const int idx = tid + k * 256;
                const int rr = idx >> 7, c4 = idx & 127;
                cp16(&s_buf[bsel][rr][c4],
                     base + (size_t)(row0 + rr) * rowstride4 + c4);
            }
            CP_COMMIT();
            CP_WAIT1();
        } else {
            CP_WAIT0();
        }
        __syncthreads();

        const int cb = t & 1;
        #pragma unroll
        for (int j = 0; j < 4; j++) {
            const float4* row = &s_buf[cb][grp * 4 + j][0];
            float4 x0 = row[lane];
            float4 x1 = row[32 + lane];
            float4 x2 = row[64 + lane];
            float4 x3 = row[96 + lane];

            float s0 = dot4(x0, qk0[0]) + dot4(x1, qk0[1]) + dot4(x2, qk0[2]) + dot4(x3, qk0[3]);
            float s1 = dot4(x0, qk1[0]) + dot4(x1, qk1[1]) + dot4(x2, qk1[2]) + dot4(x3, qk1[3]);
            // packed butterfly reduction (8 SHFL for both heads)
            s0 += __shfl_xor_sync(0xffffffffu, s0, 16);
            s1 += __shfl_xor_sync(0xffffffffu, s1, 16);
            float v = (lane < 16) ? s0 : s1;
            v += __shfl_xor_sync(0xffffffffu, v, 8);
            v += __shfl_xor_sync(0xffffffffu, v, 4);
            v += __shfl_xor_sync(0xffffffffu, v, 2);
            v += __shfl_xor_sync(0xffffffffu, v, 1);
            s0 = __shfl_sync(0xffffffffu, v, 0)  + sb0;
            s1 = __shfl_sync(0xffffffffu, v, 16) + sb1;

            if (s0 > m0) {
                float c = __expf(m0 - s0); m0 = s0; l0 *= c;
                #pragma unroll
                for (int k = 0; k < 16; k++) acc0[k] *= c;
            }
            float w0 = __expf(s0 - m0); l0 += w0;
            acc0[0]  += w0 * x0.x; acc0[1]  += w0 * x0.y; acc0[2]  += w0 * x0.z; acc0[3]  += w0 * x0.w;
            acc0[4]  += w0 * x1.x; acc0[5]  += w0 * x1.y; acc0[6]  += w0 * x1.z; acc0[7]  += w0 * x1.w;
            acc0[8]  += w0 * x2.x; acc0[9]  += w0 * x2.y; acc0[10] += w0 * x2.z; acc0[11] += w0 * x2.w;
            acc0[12] += w0 * x3.x; acc0[13] += w0 * x3.y; acc0[14] += w0 * x3.z; acc0[15] += w0 * x3.w;

            if (s1 > m1) {
                float c = __expf(m1 - s1); m1 = s1; l1 *= c;
                #pragma unroll
                for (int k = 0; k < 16; k++) acc1[k] *= c;
            }
            float w1 = __expf(s1 - m1); l1 += w1;
            acc1[0]  += w1 * x0.x; acc1[1]  += w1 * x0.y; acc1[2]  += w1 * x0.z; acc1[3]  += w1 * x0.w;
            acc1[4]  += w1 * x1.x; acc1[5]  += w1 * x1.y; acc1[6]  += w1 * x1.z; acc1[7]  += w1 * x1.w;
            acc1[8]  += w1 * x2.x; acc1[9]  += w1 * x2.y; acc1[10] += w1 * x2.z; acc1[11] += w1 * x2.w;
            acc1[12] += w1 * x3.x; acc1[13] += w1 * x3.y; acc1[14] += w1 * x3.z; acc1[15] += w1 * x3.w;
        }
        __syncthreads();   // everyone done with buf[cb] before it is overwritten
    }

    // ---- merge the two row-groups in smem, write ONE partial per head ----
    float4* mb = &s_buf[0][0][0];          // reuse buffer 0 (8 heads x 129 float4)
    if (grp == 1) {
        float4* a = mb + (size_t)h0 * 129;
        #pragma unroll
        for (int k = 0; k < 4; k++)
            a[k * 32 + lane] = make_float4(acc0[4*k], acc0[4*k+1], acc0[4*k+2], acc0[4*k+3]);
        if (lane == 0) { s_m[h0] = m0; s_l[h0] = l0; }
        a = mb + (size_t)(h0 + 1) * 129;
        #pragma unroll
        for (int k = 0; k < 4; k++)
            a[k * 32 + lane] = make_float4(acc1[4*k], acc1[4*k+1], acc1[4*k+2], acc1[4*k+3]);
        if (lane == 0) { s_m[h0 + 1] = m1; s_l[h0 + 1] = l1; }
    }
    __syncthreads();
    if (grp == 0) {
        // head h0
        {
            float mo = s_m[h0], lo = s_l[h0];
            float M  = fmaxf(m0, mo);
            float c0 = __expf(m0 - M), c1 = __expf(mo - M);
            float L  = l0 * c0 + lo * c1;
            const float4* a = mb + (size_t)h0 * 129;
            float* part = g_part + ((size_t)slot * Hc + h0) * PSTRIDE;
            float4* p4 = (float4*)part;
            #pragma unroll
            for (int k = 0; k < 4; k++) {
                float4 o = a[k * 32 + lane];
                p4[k * 32 + lane] = make_float4(
                    c0 * acc0[4*k]   + c1 * o.x,
                    c0 * acc0[4*k+1] + c1 * o.y,
                    c0 * acc0[4*k+2] + c1 * o.z,
                    c0 * acc0[4*k+3] + c1 * o.w);
            }
            if (lane == 0) { part[512] = M; part[513] = L; }
        }
        // head h0+1
        {
            float mo = s_m[h0 + 1], lo = s_l[h0 + 1];
            float M  = fmaxf(m1, mo);
            float c0 = __expf(m1 - M), c1 = __expf(mo - M);
            float L  = l1 * c0 + lo * c1;
            const float4* a = mb + (size_t)(h0 + 1) * 129;
            float* part = g_part + ((size_t)slot * Hc + h0 + 1) * PSTRIDE;
            float4* p4 = (float4*)part;
            #pragma unroll
            for (int k = 0; k < 4; k++) {
                float4 o = a[k * 32 + lane];
                p4[k * 32 + lane] = make_float4(
                    c0 * acc1[4*k]   + c1 * o.x,
                    c0 * acc1[4*k+1] + c1 * o.y,
                    c0 * acc1[4*k+2] + c1 * o.z,
                    c0 * acc1[4*k+3] + c1 * o.w);
            }
            if (lane == 0) { part[512] = M; part[513] = L; }
        }
    }
}

// ---------------------------------------------------------------------------
// k4a: merge chunk partials per (i,b,h) -> normalized context
//   grid NS*B*H = 384, block 128
// ---------------------------------------------------------------------------
__global__ void k4a_merge()
{
    const int id = blockIdx.x;
    const int i = id >> 7;
    const int b = (id >> 3) & 15;
    const int h = id & 7;
    const int tid = threadIdx.x;

    const int C   = 32 >> i;                  // 32, 16, 8 chunks
    const int off = (i == 0) ? 0 : (i == 1 ? 32 : 48);

    __shared__ float sm[32], sl[32], coef[32];

    if (tid < C) {
        const int slot = b * CHUNKS_PER_B + off + tid;
        const float* pp = g_part + ((size_t)slot * Hc + h) * PSTRIDE;
        sm[tid] = pp[512];
        sl[tid] = pp[513];
    }
    __syncthreads();

    float M = -1e30f;
    for (int p = 0; p < C; p++) M = fmaxf(M, sm[p]);
    float L = 0.f;
    for (int p = 0; p < C; p++) L += sl[p] * __expf(sm[p] - M);

    if (tid < C) coef[tid] = __expf(sm[tid] - M) / L;
    __syncthreads();

    float4 v = make_float4(0.f, 0.f, 0.f, 0.f);
    for (int p = 0; p < C; p++) {
        const int slot = b * CHUNKS_PER_B + off + p;
        const float4* pp4 = (const float4*)(g_part + ((size_t)slot * Hc + h) * PSTRIDE);
        v = fma4(v, coef[p], pp4[tid]);
    }
    float4* dst = (float4*)(g_ctx + (((size_t)i * Hc + h) * Bc + b) * Dc);
    dst[tid] = v;
}

// ---------------------------------------------------------------------------
// k4b: vproj partial  g_vpart[p,i,h,b,hd] = ctx[i,h,b,e0:+128] @ Wv-slice
//   grid (NS*H, ESPLIT), block 256
// ---------------------------------------------------------------------------
__global__ void k4b_vproj(const float* __restrict__ Wv)
{
    const int i  = blockIdx.x >> 3;
    const int h  = blockIdx.x & 7;
    const int e0 = blockIdx.y * 128;
    const int t  = threadIdx.x;

    __shared__ float4 Ws4[128][17];
    __shared__ float  cs[16][129];

    {
        const float* Wvi = Wv + (size_t)i * Dc * Dc;
        #pragma unroll
        for (int k = 0; k < 8; k++) {
            const int idx = t + k * 256;
            const int e = idx >> 4, hd4 = idx & 15;
            Ws4[e][hd4] = *(const float4*)(Wvi + (size_t)(e0 + e) * Dc + h * HDc + hd4 * 4);
        }
    }
    {
        const float* ctx = g_ctx + (((size_t)i * Hc + h) * Bc) * Dc;
        #pragma unroll
        for (int k = 0; k < 8; k++) {
            const int idx = t + k * 256;
            const int b = idx >> 7, e = idx & 127;
            cs[b][e] = ctx[(size_t)b * Dc + e0 + e];
        }
    }
    __syncthreads();

    const int b   = t & 15;
    const int hdL = t >> 4;
    float4 acc = make_float4(0.f, 0.f, 0.f, 0.f);
    #pragma unroll 4
    for (int e = 0; e < 128; e++)
        acc = fma4(acc, cs[b][e], Ws4[e][hdL]);

    float4* dst = (float4*)(g_vpart +
        ((((size_t)blockIdx.y * NSc + i) * Hc + h) * Bc + b) * HDc + hdL * 4);
    *dst = acc;
}

// ---------------------------------------------------------------------------
// k5: combined = sum_i sw_i * (proj_i + bv_i);  out = combined @ Wo + bo
//   grid (B,4), block 128
// ---------------------------------------------------------------------------
__global__ void k5_oproj(const float* __restrict__ Wo,
                         const float* __restrict__ bo,
                         const float* __restrict__ bv,
                         float* __restrict__ out)
{
    __shared__ float cs[Dc];
    const int b = blockIdx.x;
    const int d = blockIdx.y * 128 + threadIdx.x;

    for (int e = threadIdx.x; e < Dc; e += 128) {
        const int h = e >> 6, hd = e & 63;
        float s = 0.f;
        #pragma unroll
        for (int i = 0; i < NSc; i++) {
            float v = bv[(size_t)i * Dc + e];
            #pragma unroll
            for (int p = 0; p < ESPLIT; p++)
                v += g_vpart[((((size_t)p * NSc + i) * Hc + h) * Bc + b) * HDc + hd];
            s += g_sw[i] * v;
        }
        cs[e] = s;
    }
    __syncthreads();

    float a = bo[d];
    #pragma unroll 8
    for (int e = 0; e < Dc; e++) a += cs[e] * Wo[(size_t)e * Dc + d];
    out[b * Dc + d] = a;
}

// ---------------------------------------------------------------------------
// launch
// ---------------------------------------------------------------------------
extern "C" void kernel_launch(void* const* d_in, const int* in_sizes, int n_in,
                              void* d_out, int out_size)
{
    const float* dh   = (const float*)d_in[0];
    const float* enc  = (const float*)d_in[1];
    const float* Wq   = (const float*)d_in[2];
    const float* bq   = (const float*)d_in[3];
    const float* Wk   = (const float*)d_in[4];
    const float* bk   = (const float*)d_in[5];
    const float* Wv   = (const float*)d_in[6];
    const float* bv   = (const float*)d_in[7];
    const float* swi  = (const float*)d_in[8];
    const float* Wo   = (const float*)d_in[9];
    const float* bo   = (const float*)d_in[10];
    float* out = (float*)d_out;

    k1_qproj<<<dim3(Bc, 4), 128>>>(dh, Wq, bq, swi);
    k2_qkproj<<<dim3(NSc * Hc, ESPLIT), 256>>>(Wk, bk);
    k3_attn<<<NSLOTS, 256>>>(enc);
    k4a_merge<<<NSc * Bc * Hc, 128>>>();
    k4b_vproj<<<dim3(NSc * Hc, ESPLIT), 256>>>(Wv);
    k5_oproj<<<dim3(Bc, 4), 128>>>(Wo, bo, bv, out);
}